// round 1
// baseline (speedup 1.0000x reference)
#include <cuda_runtime.h>
#include <math.h>

// Problem constants
static constexpr int B_    = 32;
static constexpr int N_    = 2048;
static constexpr int D_    = 128;
static constexpr int HALF_ = 64;
static constexpr float DT_ = 0.01f;
static constexpr int M_ROWS = B_ * N_;   // 65536
static constexpr int BD     = B_ * D_;   // 4096

// Scratch (static device globals — no allocation allowed)
__device__ float g_h[N_ * B_ * D_];      // h in [N][B][D] layout
__device__ float g_g[N_ * B_ * D_];      // g = h @ W   in [N][B][D]
__device__ float g_t[N_ * B_ * D_];      // t = adj @ g in [N][B][D]
__device__ float g_a[M_ROWS * 256];      // MLP hidden activations [B*N][256]

__device__ __forceinline__ float4 ld4(const float* p) {
    return *reinterpret_cast<const float4*>(p);
}

// ---------------------------------------------------------------------------
// Tiled SGEMM: C[M,Ncols] = A[M,K] @ Bm[K,Ncols]  (+ epilogue variants)
// BM=BN=128, BK=8, 256 threads, 8x8 per thread.
// MODE 0: plain store.
// MODE 1: A is virtual concat(x, hz) per row (each [M,128]); epilogue
//         relu(acc + bias[col]); plain store.
// MODE 2: epilogue tanh(acc + bias[col]); scatter store transposed:
//         row r = b*2048 + n  ->  C[n*4096 + b*128 + col]   (h [N][B][D])
// ---------------------------------------------------------------------------
template <int MODE>
__global__ __launch_bounds__(256) void sgemm_k(
    const float* __restrict__ A, const float* __restrict__ A2,
    const float* __restrict__ Bm, const float* __restrict__ bias,
    float* __restrict__ C, int M, int Ncols, int K)
{
    constexpr int BM = 128, BN = 128, BK = 8, TM = 8, TN = 8;
    __shared__ float As[BK][BM];
    __shared__ float Bs[BK][BN];

    const int bx = blockIdx.x;            // N tile
    const int by = blockIdx.y;            // M tile
    const int tid = threadIdx.x;
    const int tx = tid & 15;              // 16 cols of threads
    const int ty = tid >> 4;              // 16 rows of threads

    // A tile load mapping: 128 rows x 8 cols -> one float4 per thread
    const int aRow = tid >> 1;            // 0..127
    const int aCol = (tid & 1) * 4;       // 0 or 4
    // B tile load mapping: 8 rows x 128 cols -> one float4 per thread
    const int bRow = tid >> 5;            // 0..7
    const int bCol = (tid & 31) * 4;      // 0..124

    float acc[TM][TN];
#pragma unroll
    for (int i = 0; i < TM; i++)
#pragma unroll
        for (int j = 0; j < TN; j++) acc[i][j] = 0.0f;

    const int gRow = by * BM + aRow;

    for (int kt = 0; kt < K; kt += BK) {
        // --- load A tile (transposed into smem) ---
        float4 av;
        const int gc = kt + aCol;
        if (MODE == 1) {
            // virtual concat: cols [0,128) from A(=x), [128,256) from A2(=hz)
            av = (gc < 128) ? ld4(A + (size_t)gRow * 128 + gc)
                            : ld4(A2 + (size_t)gRow * 128 + (gc - 128));
        } else {
            av = ld4(A + (size_t)gRow * K + gc);
        }
        As[aCol + 0][aRow] = av.x;
        As[aCol + 1][aRow] = av.y;
        As[aCol + 2][aRow] = av.z;
        As[aCol + 3][aRow] = av.w;

        // --- load B tile ---
        float4 bv = ld4(Bm + (size_t)(kt + bRow) * Ncols + bx * BN + bCol);
        *reinterpret_cast<float4*>(&Bs[bRow][bCol]) = bv;

        __syncthreads();

#pragma unroll
        for (int k = 0; k < BK; k++) {
            float a[TM], b[TN];
            *reinterpret_cast<float4*>(&a[0]) =
                *reinterpret_cast<const float4*>(&As[k][ty * TM]);
            *reinterpret_cast<float4*>(&a[4]) =
                *reinterpret_cast<const float4*>(&As[k][ty * TM + 4]);
            *reinterpret_cast<float4*>(&b[0]) =
                *reinterpret_cast<const float4*>(&Bs[k][tx * TN]);
            *reinterpret_cast<float4*>(&b[4]) =
                *reinterpret_cast<const float4*>(&Bs[k][tx * TN + 4]);
#pragma unroll
            for (int i = 0; i < TM; i++)
#pragma unroll
                for (int j = 0; j < TN; j++) acc[i][j] += a[i] * b[j];
        }
        __syncthreads();
    }

    // --- epilogue ---
#pragma unroll
    for (int i = 0; i < TM; i++) {
        const int row = by * BM + ty * TM + i;
#pragma unroll
        for (int j = 0; j < TN; j += 4) {
            const int col = bx * BN + tx * TN + j;
            float4 v = make_float4(acc[i][j], acc[i][j + 1],
                                   acc[i][j + 2], acc[i][j + 3]);
            if (MODE == 1) {
                float4 bs = ld4(bias + col);
                v.x = fmaxf(v.x + bs.x, 0.0f);
                v.y = fmaxf(v.y + bs.y, 0.0f);
                v.z = fmaxf(v.z + bs.z, 0.0f);
                v.w = fmaxf(v.w + bs.w, 0.0f);
                *reinterpret_cast<float4*>(&C[(size_t)row * Ncols + col]) = v;
            } else if (MODE == 2) {
                float4 bs = ld4(bias + col);
                v.x = tanhf(v.x + bs.x);
                v.y = tanhf(v.y + bs.y);
                v.z = tanhf(v.z + bs.z);
                v.w = tanhf(v.w + bs.w);
                const int nn = row & (N_ - 1);   // row % 2048
                const int bb = row >> 11;        // row / 2048
                *reinterpret_cast<float4*>(&C[nn * BD + bb * D_ + col]) = v;
            } else {
                *reinterpret_cast<float4*>(&C[(size_t)row * Ncols + col]) = v;
            }
        }
    }
}

// ---------------------------------------------------------------------------
// Elementwise half-updates. g_h/g_t in [N][B][D]; out in [B][N][D].
// One thread per float4 of the half-dim (64/4 = 16 per (n,b)).
// ---------------------------------------------------------------------------
__global__ __launch_bounds__(256) void half1_k(float* __restrict__ out)
{
    const int i  = blockIdx.x * 256 + threadIdx.x;   // 0 .. N*B*16-1
    const int d4 = (i & 15) * 4;
    const int nb = i >> 4;
    const int n  = nb >> 5;
    const int b  = nb & 31;
    const int base = nb * D_ + d4;

    float4 hv = *reinterpret_cast<const float4*>(&g_h[base]);
    float4 tv = *reinterpret_cast<const float4*>(&g_t[base]);
    hv.x += DT_ * tanhf(tv.x);
    hv.y += DT_ * tanhf(tv.y);
    hv.z += DT_ * tanhf(tv.z);
    hv.w += DT_ * tanhf(tv.w);
    *reinterpret_cast<float4*>(&g_h[base]) = hv;
    *reinterpret_cast<float4*>(&out[(b * N_ + n) * D_ + d4]) = hv;
}

__global__ __launch_bounds__(256) void half2_k(const float* __restrict__ eps,
                                               float* __restrict__ out)
{
    const int i  = blockIdx.x * 256 + threadIdx.x;
    const int d4 = (i & 15) * 4;
    const int nb = i >> 4;
    const int n  = nb >> 5;
    const int b  = nb & 31;
    const int base = nb * D_ + HALF_ + d4;

    float4 hv = *reinterpret_cast<const float4*>(&g_h[base]);
    float4 tv = *reinterpret_cast<const float4*>(&g_t[base]);
    float4 ev = *reinterpret_cast<const float4*>(&eps[(b * N_ + n) * HALF_ + d4]);
    ev.x = fminf(fmaxf(ev.x, 0.0f), 0.1f);
    ev.y = fminf(fmaxf(ev.y, 0.0f), 0.1f);
    ev.z = fminf(fmaxf(ev.z, 0.0f), 0.1f);
    ev.w = fminf(fmaxf(ev.w, 0.0f), 0.1f);
    hv.x = ev.x * (hv.x + DT_ * tanhf(tv.x));
    hv.y = ev.y * (hv.y + DT_ * tanhf(tv.y));
    hv.z = ev.z * (hv.z + DT_ * tanhf(tv.z));
    hv.w = ev.w * (hv.w + DT_ * tanhf(tv.w));
    *reinterpret_cast<float4*>(&g_h[base]) = hv;
    *reinterpret_cast<float4*>(&out[(b * N_ + n) * D_ + HALF_ + d4]) = hv;
}

// ---------------------------------------------------------------------------
extern "C" void kernel_launch(void* const* d_in, const int* /*in_sizes*/,
                              int /*n_in*/, void* d_out, int /*out_size*/)
{
    const float* x   = (const float*)d_in[0];
    const float* hz  = (const float*)d_in[1];
    const float* adj = (const float*)d_in[2];
    const float* W1  = (const float*)d_in[3];
    const float* W2  = (const float*)d_in[4];
    const float* Wa  = (const float*)d_in[5];
    const float* ba  = (const float*)d_in[6];
    const float* Wb  = (const float*)d_in[7];
    const float* bb  = (const float*)d_in[8];
    const float* eps = (const float*)d_in[9];
    float* out = (float*)d_out;

    float *h_p, *g_p, *t_p, *a_p;
    cudaGetSymbolAddress((void**)&h_p, g_h);
    cudaGetSymbolAddress((void**)&g_p, g_g);
    cudaGetSymbolAddress((void**)&t_p, g_t);
    cudaGetSymbolAddress((void**)&a_p, g_a);

    const dim3 blk(256);
    const int ew_blocks = (N_ * B_ * 16) / 256;   // 4096

    // MLP: a = relu(concat(x,hz) @ Wa + ba)   [65536,256]
    sgemm_k<1><<<dim3(256 / 128, M_ROWS / 128), blk>>>(
        x, hz, Wa, ba, a_p, M_ROWS, 256, 256);
    // h = tanh(a @ Wb + bb), scattered to [N][B][D]
    sgemm_k<2><<<dim3(1, M_ROWS / 128), blk>>>(
        a_p, nullptr, Wb, bb, h_p, M_ROWS, 128, 256);

    for (int it = 0; it < 2; ++it) {
        // g = h @ W1 ; t = adj @ g ; first-half update
        sgemm_k<0><<<dim3(1, M_ROWS / 128), blk>>>(
            h_p, nullptr, W1, nullptr, g_p, M_ROWS, 128, 128);
        sgemm_k<0><<<dim3(BD / 128, N_ / 128), blk>>>(
            adj, nullptr, g_p, nullptr, t_p, N_, BD, N_);
        half1_k<<<ew_blocks, blk>>>(out);

        // g = h @ W2 ; t = adj @ g ; second-half update (eps gating)
        sgemm_k<0><<<dim3(1, M_ROWS / 128), blk>>>(
            h_p, nullptr, W2, nullptr, g_p, M_ROWS, 128, 128);
        sgemm_k<0><<<dim3(BD / 128, N_ / 128), blk>>>(
            adj, nullptr, g_p, nullptr, t_p, N_, BD, N_);
        half2_k<<<ew_blocks, blk>>>(eps, out);
    }
}

// round 3
// speedup vs baseline: 4.8203x; 4.8203x over previous
#include <cuda_runtime.h>
#include <cuda_bf16.h>
#include <math.h>
#include <stdint.h>

// Problem constants
static constexpr int B_    = 32;
static constexpr int N_    = 2048;
static constexpr int D_    = 128;
static constexpr int HALF_ = 64;
static constexpr float DT_ = 0.01f;
static constexpr int M_ROWS = B_ * N_;   // 65536

// Scratch (static device globals — no allocation allowed)
__device__ float g_h[M_ROWS * D_];            // h  [B][N][D] (row = b*2048+n)
__device__ float g_a[M_ROWS * 256];           // MLP hidden [B*N][256]
__device__ __nv_bfloat16 g_adjb[N_ * N_];     // adj bf16 [n][k]
__device__ __nv_bfloat16 g_gT[B_ * HALF_ * N_]; // gT [b*64+dh][node k] (2048x2048)

__device__ __forceinline__ float4 ld4(const float* p) {
    return *reinterpret_cast<const float4*>(p);
}
__device__ __forceinline__ uint32_t s2u(const void* p) {
    uint32_t r;
    asm("{ .reg .u64 t; cvta.to.shared.u64 t, %1; cvt.u32.u64 %0, t; }"
        : "=r"(r) : "l"(p));
    return r;
}
__device__ __forceinline__ void cp16(uint32_t d, const void* s) {
    asm volatile("cp.async.cg.shared.global [%0], [%1], 16;" :: "r"(d), "l"(s) : "memory");
}
__device__ __forceinline__ uint32_t swz(uint32_t o) { return o ^ ((o >> 3) & 0x70); }
__device__ __forceinline__ float tanh_fast(float x) {
    float y;
    asm("tanh.approx.f32 %0, %1;" : "=f"(y) : "f"(x));
    return y;
}
__device__ __forceinline__ void ldsm4(uint32_t (&r)[4], uint32_t addr) {
    asm volatile("ldmatrix.sync.aligned.m8n8.x4.shared.b16 {%0,%1,%2,%3}, [%4];"
                 : "=r"(r[0]), "=r"(r[1]), "=r"(r[2]), "=r"(r[3]) : "r"(addr));
}
__device__ __forceinline__ void mma16816(float (&c)[4], const uint32_t (&a)[4],
                                         const uint32_t* b) {
    asm volatile(
        "mma.sync.aligned.m16n8k16.row.col.f32.bf16.bf16.f32 "
        "{%0,%1,%2,%3}, {%4,%5,%6,%7}, {%8,%9}, {%0,%1,%2,%3};"
        : "+f"(c[0]), "+f"(c[1]), "+f"(c[2]), "+f"(c[3])
        : "r"(a[0]), "r"(a[1]), "r"(a[2]), "r"(a[3]), "r"(b[0]), "r"(b[1]));
}

// ---------------------------------------------------------------------------
// adj GEMM via mma.sync bf16 + fused half-update epilogue.
//   t[node, col] = sum_k adjb[node][k] * gT[col][k],   col = b*64 + dh.
//   HID=0: h[bn*128+dh]    += DT*tanh(t)         (also writes out)
//   HID=1: h[bn*128+64+dh]  = clamp(eps)*(h + DT*tanh(t))   (also writes out)
// CTA tile 128x128, BK=64, 3-stage cp.async, 8 warps (2 M x 4 N), warp 64x32.
// ---------------------------------------------------------------------------
static constexpr int STAGES      = 3;
static constexpr int NK          = N_ / 64;        // 32
static constexpr int TILE_B      = 16384;          // 128 rows x 128 bytes
static constexpr int STAGE_BYTES = 2 * TILE_B;
static constexpr int ADJ_SMEM    = STAGES * STAGE_BYTES;   // 96 KB

template <int HID>
__global__ __launch_bounds__(256, 1) void adj_mma_k(
    const __nv_bfloat16* __restrict__ Ab,    // adj bf16 [2048][2048]
    const __nv_bfloat16* __restrict__ Bb,    // gT [2048][2048]
    float* __restrict__ h, float* __restrict__ out,
    const float* __restrict__ eps)
{
    extern __shared__ char smem[];
    const uint32_t sb = s2u(smem);
    const int tid  = threadIdx.x;
    const int lane = tid & 31;
    const int warp = tid >> 5;
    const int wm   = warp & 1;        // 2 warps along M
    const int wn   = warp >> 1;       // 4 warps along N
    const int bx = blockIdx.x;        // col tile (bd2)
    const int by = blockIdx.y;        // node tile

    const char* aSrc = (const char*)(Ab + (size_t)(by * 128) * N_);
    const char* bSrc = (const char*)(Bb + (size_t)(bx * 128) * N_);

    float acc[4][4][4];
#pragma unroll
    for (int i = 0; i < 4; i++)
#pragma unroll
        for (int j = 0; j < 4; j++)
#pragma unroll
            for (int v = 0; v < 4; v++) acc[i][j][v] = 0.0f;

    const int ldRow = tid >> 3;       // 0..31 base rows (x4 iters -> 128)
    const int ldCol = tid & 7;

    auto issue = [&](int kt, int s) {
        const uint32_t aB = sb + s * STAGE_BYTES;
        const uint32_t bB = aB + TILE_B;
#pragma unroll
        for (int i = 0; i < 4; i++) {
            const int row = ldRow + 32 * i;
            const uint32_t so = swz((uint32_t)(row * 128 + ldCol * 16));
            const size_t gsrc = (size_t)row * (N_ * 2) + kt * 128 + ldCol * 16;
            cp16(aB + so, aSrc + gsrc);
            cp16(bB + so, bSrc + gsrc);
        }
    };

    auto compute = [&](int s) {
        const uint32_t aB = sb + s * STAGE_BYTES;
        const uint32_t bB = aB + TILE_B;
#pragma unroll
        for (int ks = 0; ks < 4; ks++) {
            const int k0b = ks * 32;                  // 16 bf16 = 32 bytes
            uint32_t af[4][4], bf[2][4];
#pragma unroll
            for (int mt = 0; mt < 4; mt++) {
                const int row = wm * 64 + mt * 16 + (lane & 15);
                const uint32_t o = (uint32_t)(row * 128 + k0b + ((lane >> 4) << 4));
                ldsm4(af[mt], aB + swz(o));
            }
#pragma unroll
            for (int p = 0; p < 2; p++) {
                const int row = wn * 32 + p * 16 + (lane & 7) + ((lane >> 4) << 3);
                const uint32_t o = (uint32_t)(row * 128 + k0b + (((lane >> 3) & 1) << 4));
                ldsm4(bf[p], bB + swz(o));
            }
#pragma unroll
            for (int mt = 0; mt < 4; mt++)
#pragma unroll
                for (int nt = 0; nt < 4; nt++)
                    mma16816(acc[mt][nt], af[mt], &bf[nt >> 1][(nt & 1) * 2]);
        }
    };

#pragma unroll
    for (int s = 0; s < STAGES - 1; s++) {
        issue(s, s);
        asm volatile("cp.async.commit_group;" ::: "memory");
    }
    for (int kt = 0; kt < NK; kt++) {
        const int f = kt + STAGES - 1;
        if (f < NK) issue(f, f % STAGES);
        asm volatile("cp.async.commit_group;" ::: "memory");
        asm volatile("cp.async.wait_group 1;" ::: "memory");
        __syncthreads();
        compute(kt % STAGES);
        __syncthreads();
    }

    // ---- fused epilogue ----
#pragma unroll
    for (int mt = 0; mt < 4; mt++) {
        const int node0 = by * 128 + wm * 64 + mt * 16 + (lane >> 2);
#pragma unroll
        for (int nt = 0; nt < 4; nt++) {
            const int col = bx * 128 + wn * 32 + nt * 8 + 2 * (lane & 3);
            const int b  = col >> 6;
            const int dh = col & 63;
#pragma unroll
            for (int r = 0; r < 2; r++) {
                const int node = node0 + r * 8;
                const float t0 = acc[mt][nt][2 * r + 0];
                const float t1 = acc[mt][nt][2 * r + 1];
                const size_t bn = (size_t)b * N_ + node;
                const size_t hi = bn * D_ + HID * HALF_ + dh;
                float2 hv = *reinterpret_cast<const float2*>(h + hi);
                if (HID == 0) {
                    hv.x += DT_ * tanh_fast(t0);
                    hv.y += DT_ * tanh_fast(t1);
                } else {
                    float2 ev = *reinterpret_cast<const float2*>(eps + bn * HALF_ + dh);
                    ev.x = fminf(fmaxf(ev.x, 0.0f), 0.1f);
                    ev.y = fminf(fmaxf(ev.y, 0.0f), 0.1f);
                    hv.x = ev.x * (hv.x + DT_ * tanh_fast(t0));
                    hv.y = ev.y * (hv.y + DT_ * tanh_fast(t1));
                }
                *reinterpret_cast<float2*>(h + hi)   = hv;
                *reinterpret_cast<float2*>(out + hi) = hv;
            }
        }
    }
}

// ---------------------------------------------------------------------------
// adj fp32 -> bf16
// ---------------------------------------------------------------------------
__global__ __launch_bounds__(256) void cvt_adj_k(const float* __restrict__ a,
                                                 __nv_bfloat16* __restrict__ o)
{
    const int i = blockIdx.x * 256 + threadIdx.x;
    float4 v = ld4(a + (size_t)i * 4);
    __nv_bfloat162 lo = __floats2bfloat162_rn(v.x, v.y);
    __nv_bfloat162 hi = __floats2bfloat162_rn(v.z, v.w);
    *reinterpret_cast<__nv_bfloat162*>(o + (size_t)i * 4)     = lo;
    *reinterpret_cast<__nv_bfloat162*>(o + (size_t)i * 4 + 2) = hi;
}

// ---------------------------------------------------------------------------
// fp32 SGEMM (MLP). MODE 1: A=concat(x,hz), relu(acc+bias).
//                   MODE 2: tanh(acc+bias) -> h.
// ---------------------------------------------------------------------------
template <int MODE>
__global__ __launch_bounds__(256) void sgemm_k(
    const float* __restrict__ A, const float* __restrict__ A2,
    const float* __restrict__ Bm, const float* __restrict__ bias,
    float* __restrict__ C, int Ncols, int K)
{
    constexpr int BM = 128, BN = 128, BK = 8, TM = 8, TN = 8;
    __shared__ float As[BK][BM];
    __shared__ float Bs[BK][BN];

    const int bx = blockIdx.x;
    const int by = blockIdx.y;
    const int tid = threadIdx.x;
    const int tx = tid & 15;
    const int ty = tid >> 4;
    const int aRow = tid >> 1;
    const int aCol = (tid & 1) * 4;
    const int bRow = tid >> 5;
    const int bCol = (tid & 31) * 4;

    float acc[TM][TN];
#pragma unroll
    for (int i = 0; i < TM; i++)
#pragma unroll
        for (int j = 0; j < TN; j++) acc[i][j] = 0.0f;

    const int gRow = by * BM + aRow;

    for (int kt = 0; kt < K; kt += BK) {
        float4 av;
        const int gc = kt + aCol;
        if (MODE == 1) {
            av = (gc < 128) ? ld4(A + (size_t)gRow * 128 + gc)
                            : ld4(A2 + (size_t)gRow * 128 + (gc - 128));
        } else {
            av = ld4(A + (size_t)gRow * K + gc);
        }
        As[aCol + 0][aRow] = av.x;
        As[aCol + 1][aRow] = av.y;
        As[aCol + 2][aRow] = av.z;
        As[aCol + 3][aRow] = av.w;

        float4 bv = ld4(Bm + (size_t)(kt + bRow) * Ncols + bx * BN + bCol);
        *reinterpret_cast<float4*>(&Bs[bRow][bCol]) = bv;

        __syncthreads();
#pragma unroll
        for (int k = 0; k < BK; k++) {
            float a[TM], b[TN];
            *reinterpret_cast<float4*>(&a[0]) =
                *reinterpret_cast<const float4*>(&As[k][ty * TM]);
            *reinterpret_cast<float4*>(&a[4]) =
                *reinterpret_cast<const float4*>(&As[k][ty * TM + 4]);
            *reinterpret_cast<float4*>(&b[0]) =
                *reinterpret_cast<const float4*>(&Bs[k][tx * TN]);
            *reinterpret_cast<float4*>(&b[4]) =
                *reinterpret_cast<const float4*>(&Bs[k][tx * TN + 4]);
#pragma unroll
            for (int i = 0; i < TM; i++)
#pragma unroll
                for (int j = 0; j < TN; j++) acc[i][j] += a[i] * b[j];
        }
        __syncthreads();
    }

#pragma unroll
    for (int i = 0; i < TM; i++) {
        const int row = by * BM + ty * TM + i;
#pragma unroll
        for (int j = 0; j < TN; j += 4) {
            const int col = bx * BN + tx * TN + j;
            float4 v = make_float4(acc[i][j], acc[i][j + 1],
                                   acc[i][j + 2], acc[i][j + 3]);
            float4 bs = ld4(bias + col);
            if (MODE == 1) {
                v.x = fmaxf(v.x + bs.x, 0.0f);
                v.y = fmaxf(v.y + bs.y, 0.0f);
                v.z = fmaxf(v.z + bs.z, 0.0f);
                v.w = fmaxf(v.w + bs.w, 0.0f);
            } else {
                v.x = tanhf(v.x + bs.x);
                v.y = tanhf(v.y + bs.y);
                v.z = tanhf(v.z + bs.z);
                v.w = tanhf(v.w + bs.w);
            }
            *reinterpret_cast<float4*>(&C[(size_t)row * Ncols + col]) = v;
        }
    }
}

// ---------------------------------------------------------------------------
// gproj: g = h @ W (fp32), keep cols [CO, CO+64), store bf16 TRANSPOSED
// into gT[b*64 + (col-CO)][node]. One 128-row tile per CTA (grid.y = 512).
// ---------------------------------------------------------------------------
template <int CO>
__global__ __launch_bounds__(256) void gproj_k(
    const float* __restrict__ A, const float* __restrict__ Bm,
    __nv_bfloat16* __restrict__ gT)
{
    constexpr int BK = 8, TM = 8, TN = 8;
    __shared__ float As[BK][128];
    __shared__ float Bs[BK][128];
    __shared__ unsigned short Ts[128 * 68];

    const int by = blockIdx.y;
    const int tid = threadIdx.x;
    const int tx = tid & 15;
    const int ty = tid >> 4;
    const int aRow = tid >> 1;
    const int aCol = (tid & 1) * 4;
    const int bRow = tid >> 5;
    const int bCol = (tid & 31) * 4;

    float acc[TM][TN];
#pragma unroll
    for (int i = 0; i < TM; i++)
#pragma unroll
        for (int j = 0; j < TN; j++) acc[i][j] = 0.0f;

    const int gRow = by * 128 + aRow;

    for (int kt = 0; kt < 128; kt += BK) {
        float4 av = ld4(A + (size_t)gRow * 128 + kt + aCol);
        As[aCol + 0][aRow] = av.x;
        As[aCol + 1][aRow] = av.y;
        As[aCol + 2][aRow] = av.z;
        As[aCol + 3][aRow] = av.w;
        float4 bv = ld4(Bm + (size_t)(kt + bRow) * 128 + bCol);
        *reinterpret_cast<float4*>(&Bs[bRow][bCol]) = bv;
        __syncthreads();
#pragma unroll
        for (int k = 0; k < BK; k++) {
            float a[TM], b[TN];
            *reinterpret_cast<float4*>(&a[0]) =
                *reinterpret_cast<const float4*>(&As[k][ty * TM]);
            *reinterpret_cast<float4*>(&a[4]) =
                *reinterpret_cast<const float4*>(&As[k][ty * TM + 4]);
            *reinterpret_cast<float4*>(&b[0]) =
                *reinterpret_cast<const float4*>(&Bs[k][tx * TN]);
            *reinterpret_cast<float4*>(&b[4]) =
                *reinterpret_cast<const float4*>(&Bs[k][tx * TN + 4]);
#pragma unroll
            for (int i = 0; i < TM; i++)
#pragma unroll
                for (int j = 0; j < TN; j++) acc[i][j] += a[i] * b[j];
        }
        __syncthreads();
    }

    // stage only the needed 64 columns as bf16
#pragma unroll
    for (int i = 0; i < TM; i++)
#pragma unroll
        for (int j = 0; j < TN; j++) {
            const int col = tx * TN + j;
            if (col >= CO && col < CO + 64) {
                __nv_bfloat16 hb = __float2bfloat16(acc[i][j]);
                Ts[(ty * TM + i) * 68 + (col - CO)] =
                    *reinterpret_cast<unsigned short*>(&hb);
            }
        }
    __syncthreads();

    // transposed, coalesced 16B stores: gT[(b*64+colp)][n0 + node]
    const int colp = tid & 63;
    const int seg  = tid >> 6;              // 0..3 -> 32 nodes each
    const int b    = by >> 4;
    const int n0   = (by & 15) * 128;
    __nv_bfloat16* dst = gT + (size_t)(b * 64 + colp) * N_ + n0 + seg * 32;
#pragma unroll
    for (int q = 0; q < 4; q++) {
        const int r0 = seg * 32 + q * 8;
        uint32_t w[4];
#pragma unroll
        for (int p = 0; p < 4; p++) {
            uint32_t lo = Ts[(r0 + 2 * p) * 68 + colp];
            uint32_t hi = Ts[(r0 + 2 * p + 1) * 68 + colp];
            w[p] = lo | (hi << 16);
        }
        *reinterpret_cast<uint4*>(dst + q * 8) = make_uint4(w[0], w[1], w[2], w[3]);
    }
}

// ---------------------------------------------------------------------------
extern "C" void kernel_launch(void* const* d_in, const int* /*in_sizes*/,
                              int /*n_in*/, void* d_out, int /*out_size*/)
{
    const float* x   = (const float*)d_in[0];
    const float* hz  = (const float*)d_in[1];
    const float* adj = (const float*)d_in[2];
    const float* W1  = (const float*)d_in[3];
    const float* W2  = (const float*)d_in[4];
    const float* Wa  = (const float*)d_in[5];
    const float* ba  = (const float*)d_in[6];
    const float* Wb  = (const float*)d_in[7];
    const float* bb  = (const float*)d_in[8];
    const float* eps = (const float*)d_in[9];
    float* out = (float*)d_out;

    float *h_p, *a_p;
    __nv_bfloat16 *adjb_p, *gT_p;
    cudaGetSymbolAddress((void**)&h_p, g_h);
    cudaGetSymbolAddress((void**)&a_p, g_a);
    cudaGetSymbolAddress((void**)&adjb_p, g_adjb);
    cudaGetSymbolAddress((void**)&gT_p, g_gT);

    cudaFuncSetAttribute(adj_mma_k<0>,
                         cudaFuncAttributeMaxDynamicSharedMemorySize, ADJ_SMEM);
    cudaFuncSetAttribute(adj_mma_k<1>,
                         cudaFuncAttributeMaxDynamicSharedMemorySize, ADJ_SMEM);

    const dim3 blk(256);
    const dim3 adjGrid(N_ / 128, N_ / 128);   // 16 x 16

    cvt_adj_k<<<(N_ * N_) / 1024, blk>>>(adj, adjb_p);

    // MLP: a = relu(concat(x,hz) @ Wa + ba);  h = tanh(a @ Wb + bb)
    sgemm_k<1><<<dim3(2, M_ROWS / 128), blk>>>(x, hz, Wa, ba, a_p, 256, 256);
    sgemm_k<2><<<dim3(1, M_ROWS / 128), blk>>>(a_p, nullptr, Wb, bb, h_p, 128, 256);

    for (int it = 0; it < 2; ++it) {
        gproj_k<0><<<dim3(1, M_ROWS / 128), blk>>>(h_p, W1, gT_p);
        adj_mma_k<0><<<adjGrid, blk, ADJ_SMEM>>>(adjb_p, gT_p, h_p, out, nullptr);
        gproj_k<64><<<dim3(1, M_ROWS / 128), blk>>>(h_p, W2, gT_p);
        adj_mma_k<1><<<adjGrid, blk, ADJ_SMEM>>>(adjb_p, gT_p, h_p, out, eps);
    }
}

// round 4
// speedup vs baseline: 8.7199x; 1.8090x over previous
#include <cuda_runtime.h>
#include <cuda_bf16.h>
#include <math.h>
#include <stdint.h>

// Problem constants
static constexpr int B_    = 32;
static constexpr int N_    = 2048;
static constexpr int D_    = 128;
static constexpr int HALF_ = 64;
static constexpr float DT_ = 0.01f;
static constexpr int M_ROWS = B_ * N_;   // 65536

// Scratch (static device globals)
__device__ float         g_h  [M_ROWS * D_];      // h fp32 [B][N][D]
__device__ __nv_bfloat16 g_hb [M_ROWS * D_];      // bf16 mirror of h
__device__ __nv_bfloat16 g_adjb[N_ * N_];         // adj bf16
__device__ __nv_bfloat16 g_gT [N_ * N_];          // gT [b*64+dh][node]
__device__ __nv_bfloat16 g_xh_hi[M_ROWS * 256];   // concat(x,hz) hi
__device__ __nv_bfloat16 g_xh_lo[M_ROWS * 256];   // concat(x,hz) lo
__device__ __nv_bfloat16 g_a_hi [M_ROWS * 256];   // relu hidden hi
__device__ __nv_bfloat16 g_a_lo [M_ROWS * 256];   // relu hidden lo
__device__ __nv_bfloat16 g_WaT_hi[256 * 256], g_WaT_lo[256 * 256];
__device__ __nv_bfloat16 g_WbT_hi[128 * 256], g_WbT_lo[128 * 256];
__device__ __nv_bfloat16 g_W1Tb[64 * 128], g_W2Tb[64 * 128];

__device__ __forceinline__ float4 ld4(const float* p) {
    return *reinterpret_cast<const float4*>(p);
}
__device__ __forceinline__ uint32_t s2u(const void* p) {
    uint32_t r;
    asm("{ .reg .u64 t; cvta.to.shared.u64 t, %1; cvt.u32.u64 %0, t; }"
        : "=r"(r) : "l"(p));
    return r;
}
__device__ __forceinline__ void cp16(uint32_t d, const void* s) {
    asm volatile("cp.async.cg.shared.global [%0], [%1], 16;" :: "r"(d), "l"(s) : "memory");
}
__device__ __forceinline__ uint32_t swz(uint32_t o) { return o ^ ((o >> 3) & 0x70); }
__device__ __forceinline__ float tanh_fast(float x) {
    float y;
    asm("tanh.approx.f32 %0, %1;" : "=f"(y) : "f"(x));
    return y;
}
__device__ __forceinline__ void ldsm4(uint32_t (&r)[4], uint32_t addr) {
    asm volatile("ldmatrix.sync.aligned.m8n8.x4.shared.b16 {%0,%1,%2,%3}, [%4];"
                 : "=r"(r[0]), "=r"(r[1]), "=r"(r[2]), "=r"(r[3]) : "r"(addr));
}
__device__ __forceinline__ void mma16816(float (&c)[4], const uint32_t (&a)[4],
                                         const uint32_t* b) {
    asm volatile(
        "mma.sync.aligned.m16n8k16.row.col.f32.bf16.bf16.f32 "
        "{%0,%1,%2,%3}, {%4,%5,%6,%7}, {%8,%9}, {%0,%1,%2,%3};"
        : "+f"(c[0]), "+f"(c[1]), "+f"(c[2]), "+f"(c[3])
        : "r"(a[0]), "r"(a[1]), "r"(a[2]), "r"(a[3]), "r"(b[0]), "r"(b[1]));
}
__device__ __forceinline__ void split2(float v, __nv_bfloat16& hi, __nv_bfloat16& lo) {
    hi = __float2bfloat16(v);
    lo = __float2bfloat16(v - __bfloat162float(hi));
}
__device__ __forceinline__ __nv_bfloat162 pack2(__nv_bfloat16 a, __nv_bfloat16 b) {
    __nv_bfloat162 r; r.x = a; r.y = b; return r;
}

// ===========================================================================
// Conversion kernels
// ===========================================================================
__global__ __launch_bounds__(256) void cvt_adj_k(const float* __restrict__ a)
{
    const int i = blockIdx.x * 256 + threadIdx.x;
    float4 v = ld4(a + (size_t)i * 4);
    *reinterpret_cast<__nv_bfloat162*>(g_adjb + (size_t)i * 4)     =
        __floats2bfloat162_rn(v.x, v.y);
    *reinterpret_cast<__nv_bfloat162*>(g_adjb + (size_t)i * 4 + 2) =
        __floats2bfloat162_rn(v.z, v.w);
}

__global__ __launch_bounds__(256) void cvt_xh_k(const float* __restrict__ x,
                                                const float* __restrict__ hz)
{
    const int i = blockIdx.x * 256 + threadIdx.x;     // 2 * 2097152 float4s
    const bool isHz = i >= 2097152;
    const int j = isHz ? i - 2097152 : i;
    const int row = j >> 5;
    const int c4  = (j & 31) * 4;
    float4 v = ld4((isHz ? hz : x) + (size_t)row * 128 + c4);
    __nv_bfloat16 h0, l0, h1, l1, h2, l2, h3, l3;
    split2(v.x, h0, l0); split2(v.y, h1, l1);
    split2(v.z, h2, l2); split2(v.w, h3, l3);
    const size_t o = (size_t)row * 256 + (isHz ? 128 : 0) + c4;
    *reinterpret_cast<__nv_bfloat162*>(g_xh_hi + o)     = pack2(h0, h1);
    *reinterpret_cast<__nv_bfloat162*>(g_xh_hi + o + 2) = pack2(h2, h3);
    *reinterpret_cast<__nv_bfloat162*>(g_xh_lo + o)     = pack2(l0, l1);
    *reinterpret_cast<__nv_bfloat162*>(g_xh_lo + o + 2) = pack2(l2, l3);
}

__global__ __launch_bounds__(256) void cvt_w_k(const float* __restrict__ Wa,
                                               const float* __restrict__ Wb,
                                               const float* __restrict__ W1,
                                               const float* __restrict__ W2)
{
    const int i = blockIdx.x * 256 + threadIdx.x;
    if (i < 65536) {                     // WaT[n][k] = Wa[k][n]
        const int n = i >> 8, k = i & 255;
        __nv_bfloat16 hi, lo;
        split2(Wa[k * 256 + n], hi, lo);
        g_WaT_hi[i] = hi; g_WaT_lo[i] = lo;
    } else if (i < 65536 + 32768) {      // WbT[n][k] = Wb[k][n]
        const int j = i - 65536;
        const int n = j >> 8, k = j & 255;
        __nv_bfloat16 hi, lo;
        split2(Wb[k * 128 + n], hi, lo);
        g_WbT_hi[j] = hi; g_WbT_lo[j] = lo;
    } else if (i < 65536 + 32768 + 8192) {   // W1Tb[dh][k] = W1[k][dh]
        const int j = i - 65536 - 32768;
        const int dh = j >> 7, k = j & 127;
        g_W1Tb[j] = __float2bfloat16(W1[k * 128 + dh]);
    } else if (i < 65536 + 32768 + 16384) {  // W2Tb[dh][k] = W2[k][64+dh]
        const int j = i - 65536 - 32768 - 8192;
        const int dh = j >> 7, k = j & 127;
        g_W2Tb[j] = __float2bfloat16(W2[k * 128 + 64 + dh]);
    }
}

// ===========================================================================
// MLP GEMM (bf16x3 split): C = act(A @ W^T + bias)
//   MODE 1: relu -> g_a_hi/g_a_lo.   MODE 2: tanh -> g_h (fp32) + g_hb (bf16)
// CTA 128x128, K=256 in 4 chunks of 64, 3-stage cp.async pipeline.
// Per-stage smem: Ahi,Alo,Bhi,Blo @ 16KB each = 64KB. 3 stages = 192KB.
// ===========================================================================
static constexpr int MLP_STG_B = 65536;
static constexpr int MLP_SMEM  = 3 * MLP_STG_B;   // 196608

template <int MODE>
__global__ __launch_bounds__(256, 1) void mlp_mma_k(
    const __nv_bfloat16* __restrict__ Ahi, const __nv_bfloat16* __restrict__ Alo,
    const __nv_bfloat16* __restrict__ Bhi, const __nv_bfloat16* __restrict__ Blo,
    const float* __restrict__ bias)
{
    extern __shared__ char smem[];
    const uint32_t sb = s2u(smem);
    const int tid  = threadIdx.x;
    const int lane = tid & 31;
    const int warp = tid >> 5;
    const int wm   = warp & 1;       // 2 warps M (64 each)
    const int wn   = warp >> 1;      // 4 warps N (32 each)
    const int bx = blockIdx.x;
    const int by = blockIdx.y;

    float acc[4][4][4];
#pragma unroll
    for (int i = 0; i < 4; i++)
#pragma unroll
        for (int j = 0; j < 4; j++)
#pragma unroll
            for (int v = 0; v < 4; v++) acc[i][j][v] = 0.0f;

    const int ldRow = tid >> 1;          // 0..127
    const int ldCol = (tid & 1) * 4;     // 4 x 16B each

    auto issue = [&](int c, int s) {
        const uint32_t st = sb + s * MLP_STG_B;
        const size_t aOff = (size_t)(by * 128 + ldRow) * 256 + c * 64;
        const size_t bOff = (size_t)(bx * 128 + ldRow) * 256 + c * 64;
#pragma unroll
        for (int j = 0; j < 4; j++) {
            const uint32_t so = swz((uint32_t)(ldRow * 128 + (ldCol + j) * 16));
            const int e = (ldCol + j) * 8;
            cp16(st + so,          Ahi + aOff + e);
            cp16(st + 16384 + so,  Alo + aOff + e);
            cp16(st + 32768 + so,  Bhi + bOff + e);
            cp16(st + 49152 + so,  Blo + bOff + e);
        }
    };

    auto compute = [&](int s) {
        const uint32_t st = sb + s * MLP_STG_B;
#pragma unroll
        for (int ks = 0; ks < 4; ks++) {
            const int k0b = ks * 32;
            uint32_t ah[4][4], al[4][4], bh[2][4], bl[2][4];
#pragma unroll
            for (int mt = 0; mt < 4; mt++) {
                const int row = wm * 64 + mt * 16 + (lane & 15);
                const uint32_t o = swz((uint32_t)(row * 128 + k0b + ((lane >> 4) << 4)));
                ldsm4(ah[mt], st + o);
                ldsm4(al[mt], st + 16384 + o);
            }
#pragma unroll
            for (int p = 0; p < 2; p++) {
                const int row = wn * 32 + p * 16 + (lane & 7) + ((lane >> 4) << 3);
                const uint32_t o = swz((uint32_t)(row * 128 + k0b + (((lane >> 3) & 1) << 4)));
                ldsm4(bh[p], st + 32768 + o);
                ldsm4(bl[p], st + 49152 + o);
            }
#pragma unroll
            for (int mt = 0; mt < 4; mt++)
#pragma unroll
                for (int nt = 0; nt < 4; nt++) {
                    const uint32_t* bhp = &bh[nt >> 1][(nt & 1) * 2];
                    const uint32_t* blp = &bl[nt >> 1][(nt & 1) * 2];
                    mma16816(acc[mt][nt], ah[mt], bhp);
                    mma16816(acc[mt][nt], ah[mt], blp);
                    mma16816(acc[mt][nt], al[mt], bhp);
                }
        }
    };

    issue(0, 0);
    asm volatile("cp.async.commit_group;" ::: "memory");
    issue(1, 1);
    asm volatile("cp.async.commit_group;" ::: "memory");
    for (int kt = 0; kt < 4; kt++) {
        asm volatile("cp.async.wait_group 1;" ::: "memory");
        __syncthreads();
        compute(kt % 3);
        if (kt + 2 < 4) issue(kt + 2, (kt + 2) % 3);
        asm volatile("cp.async.commit_group;" ::: "memory");
    }

    // epilogue
#pragma unroll
    for (int mt = 0; mt < 4; mt++) {
        const int row0 = by * 128 + wm * 64 + mt * 16 + (lane >> 2);
#pragma unroll
        for (int nt = 0; nt < 4; nt++) {
            const int col = bx * 128 + wn * 32 + nt * 8 + 2 * (lane & 3);
            const float b0 = bias[col], b1 = bias[col + 1];
#pragma unroll
            for (int r = 0; r < 2; r++) {
                const int row = row0 + r * 8;
                float v0 = acc[mt][nt][2 * r + 0] + b0;
                float v1 = acc[mt][nt][2 * r + 1] + b1;
                if (MODE == 1) {
                    v0 = fmaxf(v0, 0.0f);
                    v1 = fmaxf(v1, 0.0f);
                    __nv_bfloat16 h0, l0, h1, l1;
                    split2(v0, h0, l0); split2(v1, h1, l1);
                    const size_t o = (size_t)row * 256 + col;
                    *reinterpret_cast<__nv_bfloat162*>(g_a_hi + o) = pack2(h0, h1);
                    *reinterpret_cast<__nv_bfloat162*>(g_a_lo + o) = pack2(l0, l1);
                } else {
                    v0 = tanhf(v0);
                    v1 = tanhf(v1);
                    const size_t o = (size_t)row * 128 + col;
                    *reinterpret_cast<float2*>(g_h + o) = make_float2(v0, v1);
                    *reinterpret_cast<__nv_bfloat162*>(g_hb + o) =
                        __floats2bfloat162_rn(v0, v1);
                }
            }
        }
    }
}

// ===========================================================================
// gproj (bf16 mma): gT[b*64+dh][node] = sum_k hb[bn][k] * WTb[dh][k]
// CTA: 128 rows x 64 cols, K=128 (2 chunks), no pipeline (all loads upfront).
// 8 warps: wm = warp&3 (M 4x32), wn = warp>>2 (N 2x32).
// ===========================================================================
static constexpr int GP_SMEM = 49152 + 128 * 68 * 2;   // 66560

__global__ __launch_bounds__(256, 1) void gproj_k(
    const __nv_bfloat16* __restrict__ WTb, __nv_bfloat16* __restrict__ gT)
{
    extern __shared__ char smem[];
    const uint32_t sb = s2u(smem);
    unsigned short* Ts = reinterpret_cast<unsigned short*>(smem + 49152);
    const int tid  = threadIdx.x;
    const int lane = tid & 31;
    const int warp = tid >> 5;
    const int wm   = warp & 3;
    const int wn   = warp >> 2;
    const int by = blockIdx.y;

    // load A (hb rows) : 128 rows x 2 chunks x 128B
    {
        const int r = tid >> 1, half = tid & 1;
        const size_t rowOff = (size_t)(by * 128 + r) * 128;
#pragma unroll
        for (int c = 0; c < 2; c++)
#pragma unroll
            for (int j = 0; j < 4; j++) {
                const uint32_t so = swz((uint32_t)(r * 128 + (half * 4 + j) * 16));
                cp16(sb + c * 16384 + so, g_hb + rowOff + c * 64 + (half * 4 + j) * 8);
            }
    }
    // load B (WTb rows) : 64 rows x 2 chunks x 128B
    {
        const int r = tid >> 2, q = tid & 3;
#pragma unroll
        for (int c = 0; c < 2; c++)
#pragma unroll
            for (int j = 0; j < 2; j++) {
                const uint32_t so = swz((uint32_t)(r * 128 + (q * 2 + j) * 16));
                cp16(sb + 32768 + c * 8192 + so,
                     WTb + (size_t)r * 128 + c * 64 + (q * 2 + j) * 8);
            }
    }
    asm volatile("cp.async.commit_group;" ::: "memory");
    asm volatile("cp.async.wait_group 0;" ::: "memory");
    __syncthreads();

    float acc[2][4][4];
#pragma unroll
    for (int i = 0; i < 2; i++)
#pragma unroll
        for (int j = 0; j < 4; j++)
#pragma unroll
            for (int v = 0; v < 4; v++) acc[i][j][v] = 0.0f;

#pragma unroll
    for (int c = 0; c < 2; c++) {
        const uint32_t aB = sb + c * 16384;
        const uint32_t bB = sb + 32768 + c * 8192;
#pragma unroll
        for (int ks = 0; ks < 4; ks++) {
            const int k0b = ks * 32;
            uint32_t af[2][4], bf[2][4];
#pragma unroll
            for (int mt = 0; mt < 2; mt++) {
                const int row = wm * 32 + mt * 16 + (lane & 15);
                ldsm4(af[mt], aB + swz((uint32_t)(row * 128 + k0b + ((lane >> 4) << 4))));
            }
#pragma unroll
            for (int p = 0; p < 2; p++) {
                const int row = wn * 32 + p * 16 + (lane & 7) + ((lane >> 4) << 3);
                ldsm4(bf[p], bB + swz((uint32_t)(row * 128 + k0b + (((lane >> 3) & 1) << 4))));
            }
#pragma unroll
            for (int mt = 0; mt < 2; mt++)
#pragma unroll
                for (int nt = 0; nt < 4; nt++)
                    mma16816(acc[mt][nt], af[mt], &bf[nt >> 1][(nt & 1) * 2]);
        }
    }
    __syncthreads();

    // stage bf16 then transposed coalesced store
#pragma unroll
    for (int mt = 0; mt < 2; mt++) {
        const int row0 = wm * 32 + mt * 16 + (lane >> 2);
#pragma unroll
        for (int nt = 0; nt < 4; nt++) {
            const int col = wn * 32 + nt * 8 + 2 * (lane & 3);
#pragma unroll
            for (int r = 0; r < 2; r++) {
                const int row = row0 + r * 8;
                __nv_bfloat16 b0 = __float2bfloat16(acc[mt][nt][2 * r + 0]);
                __nv_bfloat16 b1 = __float2bfloat16(acc[mt][nt][2 * r + 1]);
                Ts[row * 68 + col]     = *reinterpret_cast<unsigned short*>(&b0);
                Ts[row * 68 + col + 1] = *reinterpret_cast<unsigned short*>(&b1);
            }
        }
    }
    __syncthreads();

    const int colp = tid & 63;
    const int seg  = tid >> 6;
    const int b    = by >> 4;
    const int n0   = (by & 15) * 128;
    __nv_bfloat16* dst = gT + (size_t)(b * 64 + colp) * N_ + n0 + seg * 32;
#pragma unroll
    for (int q = 0; q < 4; q++) {
        const int r0 = seg * 32 + q * 8;
        uint32_t w[4];
#pragma unroll
        for (int p = 0; p < 4; p++) {
            uint32_t lo = Ts[(r0 + 2 * p) * 68 + colp];
            uint32_t hi = Ts[(r0 + 2 * p + 1) * 68 + colp];
            w[p] = lo | (hi << 16);
        }
        *reinterpret_cast<uint4*>(dst + q * 8) = make_uint4(w[0], w[1], w[2], w[3]);
    }
}

// ===========================================================================
// adj GEMM (bf16 mma) + fused half-update epilogue (also refreshes g_hb).
// CTA 128x128, BK=64, 4-stage cp.async, 8 warps (2M x 4N).
// ===========================================================================
static constexpr int STAGES      = 4;
static constexpr int NK          = N_ / 64;
static constexpr int TILE_B      = 16384;
static constexpr int STAGE_BYTES = 2 * TILE_B;
static constexpr int ADJ_SMEM    = STAGES * STAGE_BYTES;   // 128 KB

template <int HID>
__global__ __launch_bounds__(256, 1) void adj_mma_k(
    float* __restrict__ out, const float* __restrict__ eps)
{
    extern __shared__ char smem[];
    const uint32_t sb = s2u(smem);
    const int tid  = threadIdx.x;
    const int lane = tid & 31;
    const int warp = tid >> 5;
    const int wm   = warp & 1;
    const int wn   = warp >> 1;
    const int bx = blockIdx.x;
    const int by = blockIdx.y;

    const char* aSrc = (const char*)(g_adjb + (size_t)(by * 128) * N_);
    const char* bSrc = (const char*)(g_gT   + (size_t)(bx * 128) * N_);

    float acc[4][4][4];
#pragma unroll
    for (int i = 0; i < 4; i++)
#pragma unroll
        for (int j = 0; j < 4; j++)
#pragma unroll
            for (int v = 0; v < 4; v++) acc[i][j][v] = 0.0f;

    const int ldRow = tid >> 3;
    const int ldCol = tid & 7;

    auto issue = [&](int kt, int s) {
        const uint32_t aB = sb + s * STAGE_BYTES;
        const uint32_t bB = aB + TILE_B;
#pragma unroll
        for (int i = 0; i < 4; i++) {
            const int row = ldRow + 32 * i;
            const uint32_t so = swz((uint32_t)(row * 128 + ldCol * 16));
            const size_t gsrc = (size_t)row * (N_ * 2) + kt * 128 + ldCol * 16;
            cp16(aB + so, aSrc + gsrc);
            cp16(bB + so, bSrc + gsrc);
        }
    };

    auto compute = [&](int s) {
        const uint32_t aB = sb + s * STAGE_BYTES;
        const uint32_t bB = aB + TILE_B;
#pragma unroll
        for (int ks = 0; ks < 4; ks++) {
            const int k0b = ks * 32;
            uint32_t af[4][4], bf[2][4];
#pragma unroll
            for (int mt = 0; mt < 4; mt++) {
                const int row = wm * 64 + mt * 16 + (lane & 15);
                ldsm4(af[mt], aB + swz((uint32_t)(row * 128 + k0b + ((lane >> 4) << 4))));
            }
#pragma unroll
            for (int p = 0; p < 2; p++) {
                const int row = wn * 32 + p * 16 + (lane & 7) + ((lane >> 4) << 3);
                ldsm4(bf[p], bB + swz((uint32_t)(row * 128 + k0b + (((lane >> 3) & 1) << 4))));
            }
#pragma unroll
            for (int mt = 0; mt < 4; mt++)
#pragma unroll
                for (int nt = 0; nt < 4; nt++)
                    mma16816(acc[mt][nt], af[mt], &bf[nt >> 1][(nt & 1) * 2]);
        }
    };

#pragma unroll
    for (int s = 0; s < STAGES - 1; s++) {
        issue(s, s);
        asm volatile("cp.async.commit_group;" ::: "memory");
    }
    for (int kt = 0; kt < NK; kt++) {
        asm volatile("cp.async.wait_group 2;" ::: "memory");
        __syncthreads();
        compute(kt & 3);
        const int f = kt + STAGES - 1;
        if (f < NK) issue(f, f & 3);
        asm volatile("cp.async.commit_group;" ::: "memory");
    }

    // fused epilogue: half-update into h (fp32), hb (bf16), out
#pragma unroll
    for (int mt = 0; mt < 4; mt++) {
        const int node0 = by * 128 + wm * 64 + mt * 16 + (lane >> 2);
#pragma unroll
        for (int nt = 0; nt < 4; nt++) {
            const int col = bx * 128 + wn * 32 + nt * 8 + 2 * (lane & 3);
            const int b  = col >> 6;
            const int dh = col & 63;
#pragma unroll
            for (int r = 0; r < 2; r++) {
                const int node = node0 + r * 8;
                const float t0 = acc[mt][nt][2 * r + 0];
                const float t1 = acc[mt][nt][2 * r + 1];
                const size_t bn = (size_t)b * N_ + node;
                const size_t hi = bn * D_ + HID * HALF_ + dh;
                float2 hv = *reinterpret_cast<const float2*>(g_h + hi);
                if (HID == 0) {
                    hv.x += DT_ * tanh_fast(t0);
                    hv.y += DT_ * tanh_fast(t1);
                } else {
                    float2 ev = *reinterpret_cast<const float2*>(eps + bn * HALF_ + dh);
                    ev.x = fminf(fmaxf(ev.x, 0.0f), 0.1f);
                    ev.y = fminf(fmaxf(ev.y, 0.0f), 0.1f);
                    hv.x = ev.x * (hv.x + DT_ * tanh_fast(t0));
                    hv.y = ev.y * (hv.y + DT_ * tanh_fast(t1));
                }
                *reinterpret_cast<float2*>(g_h + hi) = hv;
                *reinterpret_cast<__nv_bfloat162*>(g_hb + hi) =
                    __floats2bfloat162_rn(hv.x, hv.y);
                *reinterpret_cast<float2*>(out + hi) = hv;
            }
        }
    }
}

// ===========================================================================
extern "C" void kernel_launch(void* const* d_in, const int* /*in_sizes*/,
                              int /*n_in*/, void* d_out, int /*out_size*/)
{
    const float* x   = (const float*)d_in[0];
    const float* hz  = (const float*)d_in[1];
    const float* adj = (const float*)d_in[2];
    const float* W1  = (const float*)d_in[3];
    const float* W2  = (const float*)d_in[4];
    const float* Wa  = (const float*)d_in[5];
    const float* ba  = (const float*)d_in[6];
    const float* Wb  = (const float*)d_in[7];
    const float* bb  = (const float*)d_in[8];
    const float* eps = (const float*)d_in[9];
    float* out = (float*)d_out;

    __nv_bfloat16 *xh_hi, *xh_lo, *WaT_hi, *WaT_lo;
    __nv_bfloat16 *a_hi, *a_lo, *WbT_hi, *WbT_lo;
    __nv_bfloat16 *W1Tb, *W2Tb, *gT_p;
    cudaGetSymbolAddress((void**)&xh_hi, g_xh_hi);
    cudaGetSymbolAddress((void**)&xh_lo, g_xh_lo);
    cudaGetSymbolAddress((void**)&WaT_hi, g_WaT_hi);
    cudaGetSymbolAddress((void**)&WaT_lo, g_WaT_lo);
    cudaGetSymbolAddress((void**)&a_hi, g_a_hi);
    cudaGetSymbolAddress((void**)&a_lo, g_a_lo);
    cudaGetSymbolAddress((void**)&WbT_hi, g_WbT_hi);
    cudaGetSymbolAddress((void**)&WbT_lo, g_WbT_lo);
    cudaGetSymbolAddress((void**)&W1Tb, g_W1Tb);
    cudaGetSymbolAddress((void**)&W2Tb, g_W2Tb);
    cudaGetSymbolAddress((void**)&gT_p, g_gT);

    cudaFuncSetAttribute(mlp_mma_k<1>,
                         cudaFuncAttributeMaxDynamicSharedMemorySize, MLP_SMEM);
    cudaFuncSetAttribute(mlp_mma_k<2>,
                         cudaFuncAttributeMaxDynamicSharedMemorySize, MLP_SMEM);
    cudaFuncSetAttribute(gproj_k,
                         cudaFuncAttributeMaxDynamicSharedMemorySize, GP_SMEM);
    cudaFuncSetAttribute(adj_mma_k<0>,
                         cudaFuncAttributeMaxDynamicSharedMemorySize, ADJ_SMEM);
    cudaFuncSetAttribute(adj_mma_k<1>,
                         cudaFuncAttributeMaxDynamicSharedMemorySize, ADJ_SMEM);

    const dim3 blk(256);
    const dim3 adjGrid(N_ / 128, N_ / 128);

    cvt_adj_k<<<(N_ * N_) / 1024, blk>>>(adj);
    cvt_xh_k<<<16384, blk>>>(x, hz);
    cvt_w_k<<<448, blk>>>(Wa, Wb, W1, W2);

    // MLP: a = relu(xh @ Wa + ba);  h = tanh(a @ Wb + bb)
    mlp_mma_k<1><<<dim3(2, M_ROWS / 128), blk, MLP_SMEM>>>(
        xh_hi, xh_lo, WaT_hi, WaT_lo, ba);
    mlp_mma_k<2><<<dim3(1, M_ROWS / 128), blk, MLP_SMEM>>>(
        a_hi, a_lo, WbT_hi, WbT_lo, bb);

    for (int it = 0; it < 2; ++it) {
        gproj_k<<<dim3(1, M_ROWS / 128), blk, GP_SMEM>>>(W1Tb, gT_p);
        adj_mma_k<0><<<adjGrid, blk, ADJ_SMEM>>>(out, eps);
        gproj_k<<<dim3(1, M_ROWS / 128), blk, GP_SMEM>>>(W2Tb, gT_p);
        adj_mma_k<1><<<adjGrid, blk, ADJ_SMEM>>>(out, eps);
    }
}